// round 12
// baseline (speedup 1.0000x reference)
#include <cuda_runtime.h>
#include <cstdint>
#include <math.h>

#define LEAK 0.01f

// Shapes: B=1024, H=512, half=256
// c1: 2->64 3x3 s1 p1 (32x32); c2: 64->128 3x3 s2 p1 (->16x16); c3: 128x16x16->256
// GRU: H=512

// ---------------- static scratch ----------------
__device__ float g_c1 [1024L * 32 * 32 * 64];   // NHWC c1 out (tf32-rounded)
__device__ float g_c2 [1024L * 128 * 256];      // [img][oc][px] (rounded) = c3 A rows
__device__ float g_w2 [128 * 9 * 64];           // c2 weights [oc][tap][ic] (rounded)
__device__ float g_w3 [256L * 32768];           // c3 weights rounded
__device__ float g_wih[1536 * 512];             // rounded
__device__ float g_whh[1536 * 512];             // rounded
__device__ float g_h0 [1024 * 512];             // rounded last_hh
__device__ float g_x  [1024 * 512];             // concat(pre_vec, height_vec), rounded
__device__ float g_c3p[32L * 1024 * 256];       // c3 split-K partials [z][b][o]
__device__ float g_gi [1024 * 1536];
__device__ float g_gh [1024 * 1536];

// ---------------- helpers ----------------
__device__ __forceinline__ uint32_t smem_u32(const void* p) {
    uint32_t a;
    asm("{ .reg .u64 t; cvta.to.shared.u64 t, %1; cvt.u32.u64 %0, t; }" : "=r"(a) : "l"(p));
    return a;
}
__device__ __forceinline__ float rndtf32(float f) {
    uint32_t r;
    asm("cvt.rna.tf32.f32 %0, %1;" : "=r"(r) : "f"(f));
    return __uint_as_float(r);
}
__device__ __forceinline__ void mma_tf32(float* c, uint32_t a0, uint32_t a1,
                                         uint32_t a2, uint32_t a3,
                                         uint32_t b0, uint32_t b1) {
    asm volatile(
        "mma.sync.aligned.m16n8k8.row.col.f32.tf32.tf32.f32 "
        "{%0,%1,%2,%3}, {%4,%5,%6,%7}, {%8,%9}, {%0,%1,%2,%3};"
        : "+f"(c[0]), "+f"(c[1]), "+f"(c[2]), "+f"(c[3])
        : "r"(a0), "r"(a1), "r"(a2), "r"(a3), "r"(b0), "r"(b1));
}
#define CP_ASYNC16(dst, src) \
    asm volatile("cp.async.cg.shared.global [%0], [%1], 16;" :: "r"(dst), "l"(src) : "memory")
#define CP_ASYNC16Z(dst, src, sz) \
    asm volatile("cp.async.cg.shared.global [%0], [%1], 16, %2;" :: "r"(dst), "l"(src), "r"(sz) : "memory")
#define CP_COMMIT() asm volatile("cp.async.commit_group;" ::: "memory")
#define CP_WAIT0()  asm volatile("cp.async.wait_group 0;" ::: "memory")
#define CP_WAIT1()  asm volatile("cp.async.wait_group 1;" ::: "memory")

// BK=16 tile: 128 rows x 4 float4 (64B/row), two rows packed per 128B line.
// f4 offset: lin = row*4 + j ; off = (lin & ~7) | ((lin&7) ^ ((lin>>3)&7))
__device__ __forceinline__ int swz16(int row, int j) {
    int lin = row * 4 + j;
    return (lin & ~7) | ((lin & 7) ^ ((lin >> 3) & 7));
}

// ---- GEMM core: BM=128 BN=128 BK=16, 4 warps (2M x 2N), warp tile 64x64 ----
__device__ __forceinline__ void compute_stage16(uint32_t aS, uint32_t bS, int lane,
                                                int wm, int wn,
                                                float (&acc)[4][8][4]) {
    int t = lane >> 3, r8 = lane & 7;
    int rowA = wm * 64 + (t & 1) * 8 + r8;
    int thA = t >> 1;
    int rowB = wn * 64 + (t >> 1) * 8 + r8;
    int thB = t & 1;
#pragma unroll
    for (int kk = 0; kk < 2; kk++) {
        uint32_t a[4][4];
#pragma unroll
        for (int mt = 0; mt < 4; mt++) {
            uint32_t adr = aS + (uint32_t)(swz16(rowA + mt * 16, kk * 2 + thA) << 4);
            asm volatile("ldmatrix.sync.aligned.m8n8.x4.shared.b16 {%0,%1,%2,%3}, [%4];"
                         : "=r"(a[mt][0]), "=r"(a[mt][1]), "=r"(a[mt][2]), "=r"(a[mt][3])
                         : "r"(adr));
        }
        uint32_t b[8][2];
#pragma unroll
        for (int p = 0; p < 4; p++) {
            uint32_t adr = bS + (uint32_t)(swz16(rowB + p * 16, kk * 2 + thB) << 4);
            uint32_t r0, r1, r2, r3;
            asm volatile("ldmatrix.sync.aligned.m8n8.x4.shared.b16 {%0,%1,%2,%3}, [%4];"
                         : "=r"(r0), "=r"(r1), "=r"(r2), "=r"(r3) : "r"(adr));
            b[p * 2][0] = r0; b[p * 2][1] = r1;
            b[p * 2 + 1][0] = r2; b[p * 2 + 1][1] = r3;
        }
#pragma unroll
        for (int mt = 0; mt < 4; mt++)
#pragma unroll
            for (int nt = 0; nt < 8; nt++)
                mma_tf32(acc[mt][nt], a[mt][0], a[mt][1], a[mt][2], a[mt][3],
                         b[nt][0], b[nt][1]);
    }
}

// ---------------- fused prep: rounding copies + repack + prebox ----------------
__global__ void k_prep(const float4* __restrict__ c3_w,
                       const float4* __restrict__ w_ih,
                       const float4* __restrict__ w_hh,
                       const float4* __restrict__ last_hh,
                       const float* __restrict__ c2_w,
                       const float* __restrict__ pb,
                       const float* __restrict__ pbw,
                       const float* __restrict__ pbb) {
    int blk = blockIdx.x, tid = threadIdx.x;
    if (blk < 9728) {
        const float4* src;
        float4* dst;
        int i, n4;
        if (blk < 8192)      { src = c3_w;    dst = (float4*)g_w3;  i = blk * 256 + tid;           n4 = 2097152; }
        else if (blk < 8960) { src = w_ih;    dst = (float4*)g_wih; i = (blk - 8192) * 256 + tid;  n4 = 196608; }
        else                 { src = w_hh;    dst = (float4*)g_whh; i = (blk - 8960) * 256 + tid;  n4 = 196608; }
        if (i < n4) {
            float4 v = src[i];
            v.x = rndtf32(v.x); v.y = rndtf32(v.y); v.z = rndtf32(v.z); v.w = rndtf32(v.w);
            dst[i] = v;
        }
    } else if (blk < 10240) {
        int i = (blk - 9728) * 256 + tid;     // 131072 float4
        float4 v = last_hh[i];
        v.x = rndtf32(v.x); v.y = rndtf32(v.y); v.z = rndtf32(v.z); v.w = rndtf32(v.w);
        ((float4*)g_h0)[i] = v;
    } else if (blk < 10528) {
        int idx = (blk - 10240) * 256 + tid;  // 128*576
        int oc = idx / 576, rem = idx - oc * 576;
        int tap = rem >> 6, ic = rem & 63;
        g_w2[idx] = rndtf32(c2_w[oc * 576 + ic * 9 + tap]);
    } else {
        int idx = (blk - 10528) * 256 + tid;  // 1024*256
        int b = idx >> 8, o = idx & 255;
        float acc = pbb[o];
        acc = fmaf(pb[b * 3 + 0], pbw[o * 3 + 0], acc);
        acc = fmaf(pb[b * 3 + 1], pbw[o * 3 + 1], acc);
        acc = fmaf(pb[b * 3 + 2], pbw[o * 3 + 2], acc);
        g_x[b * 512 + o] = rndtf32(acc);
    }
}

// ---------------- c1: direct conv -> NHWC (rounded) ----------------
__global__ __launch_bounds__(256) void k_c1(const float* __restrict__ hm,
                                            const float* __restrict__ w,
                                            const float* __restrict__ bias) {
    __shared__ float in_s[2 * 34 * 34];
    __shared__ __align__(16) float w_s[64 * 20];   // stride-20, 16B aligned per oc
    __shared__ float b_s[64];
    int img = blockIdx.x, tid = threadIdx.x;

    for (int i = tid; i < 2 * 34 * 34; i += 256) in_s[i] = 0.f;
    __syncthreads();
    for (int i = tid; i < 2048; i += 256) {
        int ic = i >> 10, p = i & 1023, y = p >> 5, x = p & 31;
        in_s[ic * 1156 + (y + 1) * 34 + (x + 1)] = hm[img * 2048 + i];
    }
    for (int i = tid; i < 1152; i += 256) {
        int oc = i / 18, k = i - oc * 18;
        w_s[oc * 20 + k] = w[i];
    }
    if (tid < 128) {
        int oc = tid >> 1;
        w_s[oc * 20 + 18 + (tid & 1)] = 0.f;
    }
    if (tid < 64) b_s[tid] = bias[tid];
    __syncthreads();

#pragma unroll
    for (int g = 0; g < 4; g++) {
        int p = tid + 256 * g;
        int y = p >> 5, x = p & 31;
        float r[18];
#pragma unroll
        for (int ic = 0; ic < 2; ic++)
#pragma unroll
            for (int kh = 0; kh < 3; kh++)
#pragma unroll
                for (int kw = 0; kw < 3; kw++)
                    r[ic * 9 + kh * 3 + kw] = in_s[ic * 1156 + (y + kh) * 34 + (x + kw)];
        float4 v4[16];
        float* v = (float*)v4;
        for (int oc = 0; oc < 64; oc++) {
            float wr[20];
            const float4* wp = (const float4*)&w_s[oc * 20];
            *(float4*)&wr[0]  = wp[0];
            *(float4*)&wr[4]  = wp[1];
            *(float4*)&wr[8]  = wp[2];
            *(float4*)&wr[12] = wp[3];
            *(float4*)&wr[16] = wp[4];
            float acc = b_s[oc];
#pragma unroll
            for (int k = 0; k < 18; k++) acc = fmaf(r[k], wr[k], acc);
            acc = acc >= 0.f ? acc : LEAK * acc;
            v[oc] = rndtf32(acc);
        }
        float4* dst = (float4*)&g_c1[((long)img * 1024 + p) * 64];
#pragma unroll
        for (int q = 0; q < 16; q++) dst[q] = v4[q];
    }
}

// ---------------- c2: implicit GEMM; A+B cp.async 3-stage, BK=16 ----------------
// CTA = (img half: 128 px) x (128 oc). 128 threads, 4 warps, warp 64x64.
// K = 576 = 36 stages of 16 (tap t = s>>2, ic quarter q = s&3).
__global__ __launch_bounds__(128) void k_c2mma(const float* __restrict__ bias) {
    __shared__ __align__(16) float4 smA[1536];    // 3 x 8KB
    __shared__ __align__(16) float4 smB[1536];    // 3 x 8KB
    int tid = threadIdx.x, lane = tid & 31, w = tid >> 5;
    int wm = w & 1, wn = w >> 1;
    int img = blockIdx.x >> 1, pxl = (blockIdx.x & 1) * 128;
    int rowT = tid >> 2, jT = tid & 3;           // thread covers rows rowT+32i, col jT
    uint32_t aBase = smem_u32(smA), bBase = smem_u32(smB);

    float acc[4][8][4] = {};

    auto cpStage = [&](int s, int buf) {
        int t = s >> 2, q = s & 3;
        int ty = t / 3, tx = t - ty * 3;
        uint32_t aOff = aBase + buf * 8192, bOff = bBase + buf * 8192;
#pragma unroll
        for (int i = 0; i < 4; i++) {
            int row = rowT + 32 * i;
            int px = pxl + row, oy = px >> 4, ox = px & 15;
            int iy = 2 * oy + ty - 1, ix = 2 * ox + tx - 1;
            int ok = ((unsigned)iy < 32u && (unsigned)ix < 32u) ? 16 : 0;
            const float* srcA = ok
                ? &g_c1[(((long)img * 32 + iy) * 32 + ix) * 64 + q * 16 + jT * 4]
                : &g_c1[0];
            CP_ASYNC16Z(aOff + (uint32_t)(swz16(row, jT) << 4), srcA, ok);
            const float* srcB = &g_w2[row * 576 + t * 64 + q * 16 + jT * 4];
            CP_ASYNC16(bOff + (uint32_t)(swz16(row, jT) << 4), srcB);
        }
    };

    cpStage(0, 0); CP_COMMIT();
    cpStage(1, 1); CP_COMMIT();
    CP_WAIT1(); __syncthreads();
    int buf = 0;
    for (int s = 0; s < 36; s++) {
        if (s + 2 < 36) {
            int b2 = buf + 2; if (b2 >= 3) b2 -= 3;
            cpStage(s + 2, b2); CP_COMMIT();
        }
        compute_stage16(aBase + buf * 8192, bBase + buf * 8192, lane, wm, wn, acc);
        if (s + 1 < 36) {
            if (s + 2 < 36) CP_WAIT1(); else CP_WAIT0();
        }
        __syncthreads();
        if (++buf == 3) buf = 0;
    }

    int mr = lane >> 2, nc = (lane & 3) * 2;
#pragma unroll
    for (int mt = 0; mt < 4; mt++)
#pragma unroll
        for (int nt = 0; nt < 8; nt++) {
            int m = wm * 64 + mt * 16 + mr;
            int n = wn * 64 + nt * 8 + nc;
#pragma unroll
            for (int q = 0; q < 4; q++) {
                int mm = m + (q >> 1) * 8, oc = n + (q & 1);
                float v = acc[mt][nt][q] + __ldg(&bias[oc]);
                v = v >= 0.f ? v : LEAK * v;
                g_c2[(long)img * 32768 + (long)oc * 256 + (pxl + mm)] = rndtf32(v);
            }
        }
}

// ---------------- generic GEMM: C[M][N] = A[M,K] * B[N,K]^T ----------------
// 128 threads, 4 warps, warp 64x64. BK=16, A+B cp.async 3-stage. S = K/16 chunks.
__global__ __launch_bounds__(128) void k_gemm_mma(
    const float* __restrict__ A, int lda,
    const float* __restrict__ B, int ldb,
    float* __restrict__ C, int ldc, int S, long cSplit) {
    __shared__ __align__(16) float4 smA[1536];    // 3 x 8KB
    __shared__ __align__(16) float4 smB[1536];    // 3 x 8KB
    int tid = threadIdx.x, lane = tid & 31, w = tid >> 5;
    int wm = w & 1, wn = w >> 1;
    long m0 = blockIdx.y * 128, n0 = blockIdx.x * 128;
    long kBase = (long)blockIdx.z * S * 16;
    C += (long)blockIdx.z * cSplit;
    const float* Ap = A + m0 * lda + kBase;
    const float* Bp = B + n0 * ldb + kBase;
    int rowT = tid >> 2, jT = tid & 3;
    uint32_t aBase = smem_u32(smA), bBase = smem_u32(smB);

    float acc[4][8][4] = {};

    auto cpStage = [&](int s, int buf) {
        long k0 = (long)s * 16 + jT * 4;
        uint32_t aOff = aBase + buf * 8192, bOff = bBase + buf * 8192;
#pragma unroll
        for (int i = 0; i < 4; i++) {
            int row = rowT + 32 * i;
            uint32_t d = (uint32_t)(swz16(row, jT) << 4);
            CP_ASYNC16(aOff + d, Ap + (long)row * lda + k0);
            CP_ASYNC16(bOff + d, Bp + (long)row * ldb + k0);
        }
    };

    cpStage(0, 0); CP_COMMIT();
    cpStage(1, 1); CP_COMMIT();
    CP_WAIT1(); __syncthreads();
    int buf = 0;
    for (int s = 0; s < S; s++) {
        if (s + 2 < S) {
            int b2 = buf + 2; if (b2 >= 3) b2 -= 3;
            cpStage(s + 2, b2); CP_COMMIT();
        }
        compute_stage16(aBase + buf * 8192, bBase + buf * 8192, lane, wm, wn, acc);
        if (s + 1 < S) {
            if (s + 2 < S) CP_WAIT1(); else CP_WAIT0();
        }
        __syncthreads();
        if (++buf == 3) buf = 0;
    }

    int mr = lane >> 2, nc = (lane & 3) * 2;
#pragma unroll
    for (int mt = 0; mt < 4; mt++)
#pragma unroll
        for (int nt = 0; nt < 8; nt++) {
            long m = m0 + wm * 64 + mt * 16 + mr;
            long n = n0 + wn * 64 + nt * 8 + nc;
            *(float2*)&C[m * ldc + n] = make_float2(acc[mt][nt][0], acc[mt][nt][1]);
            *(float2*)&C[(m + 8) * ldc + n] = make_float2(acc[mt][nt][2], acc[mt][nt][3]);
        }
}

// ---------------- c3 split-K reduce + bias + leaky -> x[:, 256:] (rounded) ----
__global__ void k_c3red(const float* __restrict__ bias) {
    int idx = blockIdx.x * 256 + threadIdx.x;   // 1024*256
    int b = idx >> 8, o = idx & 255;
    float s = 0.f;
#pragma unroll
    for (int sp = 0; sp < 32; sp++) s += g_c3p[(long)sp * 262144 + idx];
    s += bias[o];
    s = s >= 0.f ? s : LEAK * s;
    g_x[b * 512 + 256 + o] = rndtf32(s);
}

// ---------------- GRU gates + output ----------------
__global__ void k_gate(const float* __restrict__ h0,
                       const float* __restrict__ bih,
                       const float* __restrict__ bhh,
                       float* __restrict__ out) {
    int idx = blockIdx.x * 256 + threadIdx.x;   // 1024*512
    int b = idx >> 9, j = idx & 511;
    float ir = g_gi[b * 1536 + j]        + bih[j];
    float iz = g_gi[b * 1536 + 512 + j]  + bih[512 + j];
    float in = g_gi[b * 1536 + 1024 + j] + bih[1024 + j];
    float hr = g_gh[b * 1536 + j]        + bhh[j];
    float hz = g_gh[b * 1536 + 512 + j]  + bhh[512 + j];
    float hn = g_gh[b * 1536 + 1024 + j] + bhh[1024 + j];
    float r = 1.f / (1.f + expf(-(ir + hr)));
    float z = 1.f / (1.f + expf(-(iz + hz)));
    float n = tanhf(in + r * hn);
    float h = (1.f - z) * n + z * h0[idx];
    out[idx] = h;
    out[1024 * 512 + idx] = h;
}

// ---------------- launch ----------------
extern "C" void kernel_launch(void* const* d_in, const int* in_sizes, int n_in,
                              void* d_out, int out_size) {
    const float* pre_box   = (const float*)d_in[0];
    const float* heightmap = (const float*)d_in[1];
    const float* last_hh   = (const float*)d_in[2];
    const float* prebox_w  = (const float*)d_in[3];
    const float* prebox_b  = (const float*)d_in[4];
    const float* c1_w      = (const float*)d_in[5];
    const float* c1_b      = (const float*)d_in[6];
    const float* c2_w      = (const float*)d_in[7];
    const float* c2_b      = (const float*)d_in[8];
    const float* c3_w      = (const float*)d_in[9];
    const float* c3_b      = (const float*)d_in[10];
    const float* w_ih      = (const float*)d_in[11];
    const float* w_hh      = (const float*)d_in[12];
    const float* b_ih      = (const float*)d_in[13];
    const float* b_hh      = (const float*)d_in[14];
    float* out = (float*)d_out;

    float *p_c2, *p_c3p, *p_x, *p_gi, *p_gh, *p_w3, *p_wih, *p_whh, *p_h0;
    cudaGetSymbolAddress((void**)&p_c2, g_c2);
    cudaGetSymbolAddress((void**)&p_c3p, g_c3p);
    cudaGetSymbolAddress((void**)&p_x, g_x);
    cudaGetSymbolAddress((void**)&p_gi, g_gi);
    cudaGetSymbolAddress((void**)&p_gh, g_gh);
    cudaGetSymbolAddress((void**)&p_w3, g_w3);
    cudaGetSymbolAddress((void**)&p_wih, g_wih);
    cudaGetSymbolAddress((void**)&p_whh, g_whh);
    cudaGetSymbolAddress((void**)&p_h0, g_h0);

    k_prep<<<11552, 256>>>((const float4*)c3_w, (const float4*)w_ih,
                           (const float4*)w_hh, (const float4*)last_hh,
                           c2_w, pre_box, prebox_w, prebox_b);
    k_c1<<<1024, 256>>>(heightmap, c1_w, c1_b);

    k_c2mma<<<2048, 128>>>(c2_b);

    // c3: M=1024, N=256, K=32768, split-K=32 (S=64 BK16-stages each)
    k_gemm_mma<<<dim3(2, 8, 32), 128>>>(p_c2, 32768, p_w3, 32768,
                                        p_c3p, 256, 64, 262144L);
    k_c3red<<<1024, 256>>>(c3_b);

    // GRU: gi = x*w_ih^T, gh = h0*w_hh^T  (M=1024, N=1536, K=512 -> S=32)
    k_gemm_mma<<<dim3(12, 8, 1), 128>>>(p_x, 512, p_wih, 512, p_gi, 1536, 32, 0);
    k_gemm_mma<<<dim3(12, 8, 1), 128>>>(p_h0, 512, p_whh, 512, p_gh, 1536, 32, 0);

    k_gate<<<2048, 256>>>(last_hh, b_ih, b_hh, out);
}

// round 14
// speedup vs baseline: 1.0747x; 1.0747x over previous
#include <cuda_runtime.h>
#include <cstdint>
#include <math.h>

#define LEAK 0.01f

// Shapes: B=1024, H=512, half=256
// c1: 2->64 3x3 s1 p1 (32x32); c2: 64->128 3x3 s2 p1 (->16x16); c3: 128x16x16->256
// GRU: H=512

// ---------------- static scratch ----------------
__device__ float g_c1 [1024L * 32 * 32 * 64];   // NHWC c1 out (tf32-rounded)
__device__ float g_c2 [1024L * 128 * 256];      // [img][oc][px] (rounded) = c3 A rows
__device__ float g_w2 [128 * 9 * 64];           // c2 weights [oc][tap][ic] (rounded)
__device__ float g_h0 [1024 * 512];             // rounded last_hh
__device__ float g_x  [1024 * 512];             // concat(pre_vec, height_vec), rounded
__device__ float g_c3p[16L * 1024 * 256];       // c3 split-K partials [z][b][o]
__device__ float g_gi [1024 * 1536];
__device__ float g_gh [1024 * 1536];

// ---------------- helpers ----------------
__device__ __forceinline__ uint32_t smem_u32(const void* p) {
    uint32_t a;
    asm("{ .reg .u64 t; cvta.to.shared.u64 t, %1; cvt.u32.u64 %0, t; }" : "=r"(a) : "l"(p));
    return a;
}
__device__ __forceinline__ float rndtf32(float f) {
    uint32_t r;
    asm("cvt.rna.tf32.f32 %0, %1;" : "=r"(r) : "f"(f));
    return __uint_as_float(r);
}
__device__ __forceinline__ void mma_tf32(float* c, uint32_t a0, uint32_t a1,
                                         uint32_t a2, uint32_t a3,
                                         uint32_t b0, uint32_t b1) {
    asm volatile(
        "mma.sync.aligned.m16n8k8.row.col.f32.tf32.tf32.f32 "
        "{%0,%1,%2,%3}, {%4,%5,%6,%7}, {%8,%9}, {%0,%1,%2,%3};"
        : "+f"(c[0]), "+f"(c[1]), "+f"(c[2]), "+f"(c[3])
        : "r"(a0), "r"(a1), "r"(a2), "r"(a3), "r"(b0), "r"(b1));
}
#define CP_ASYNC16(dst, src) \
    asm volatile("cp.async.cg.shared.global [%0], [%1], 16;" :: "r"(dst), "l"(src) : "memory")
#define CP_ASYNC16Z(dst, src, sz) \
    asm volatile("cp.async.cg.shared.global [%0], [%1], 16, %2;" :: "r"(dst), "l"(src), "r"(sz) : "memory")
#define CP_COMMIT() asm volatile("cp.async.commit_group;" ::: "memory")
#define CP_WAIT0()  asm volatile("cp.async.wait_group 0;" ::: "memory")

// ---- GEMM core: BM=128 BN=128 BK=32, 4 warps (2M x 2N), warp tile 64x64 ----
// A and B tiles in smem, float4 swizzle: o4 = row*8 + (c4 ^ (row&7))
__device__ __forceinline__ void compute_stage(uint32_t aS, uint32_t bS, int lane,
                                              int wm, int wn,
                                              float (&acc)[4][8][4]) {
    int t = lane >> 3, r8 = lane & 7;
    int rowA = wm * 64 + (t & 1) * 8 + r8;
    int thA = t >> 1;
    int rowB = wn * 64 + (t >> 1) * 8 + r8;
    int thB = t & 1;
#pragma unroll
    for (int kk = 0; kk < 4; kk++) {
        uint32_t a[4][4];
#pragma unroll
        for (int mt = 0; mt < 4; mt++) {
            uint32_t adr = aS + (uint32_t)(((((rowA + mt * 16) << 3) +
                            ((kk * 2 + thA) ^ r8))) << 4);
            asm volatile("ldmatrix.sync.aligned.m8n8.x4.shared.b16 {%0,%1,%2,%3}, [%4];"
                         : "=r"(a[mt][0]), "=r"(a[mt][1]), "=r"(a[mt][2]), "=r"(a[mt][3])
                         : "r"(adr));
        }
        uint32_t b[8][2];
#pragma unroll
        for (int p = 0; p < 4; p++) {
            uint32_t adr = bS + (uint32_t)(((((rowB + p * 16) << 3) +
                            ((kk * 2 + thB) ^ r8))) << 4);
            uint32_t r0, r1, r2, r3;
            asm volatile("ldmatrix.sync.aligned.m8n8.x4.shared.b16 {%0,%1,%2,%3}, [%4];"
                         : "=r"(r0), "=r"(r1), "=r"(r2), "=r"(r3) : "r"(adr));
            b[p * 2][0] = r0; b[p * 2][1] = r1;
            b[p * 2 + 1][0] = r2; b[p * 2 + 1][1] = r3;
        }
#pragma unroll
        for (int mt = 0; mt < 4; mt++)
#pragma unroll
            for (int nt = 0; nt < 8; nt++)
                mma_tf32(acc[mt][nt], a[mt][0], a[mt][1], a[mt][2], a[mt][3],
                         b[nt][0], b[nt][1]);
    }
}

// ---------------- fused prep: h0 rounding + repack + prebox ----------------
// block ranges: [0,512) h0 | [512,800) repack | [800,1824) prebox
__global__ void k_prep(const float4* __restrict__ last_hh,
                       const float* __restrict__ c2_w,
                       const float* __restrict__ pb,
                       const float* __restrict__ pbw,
                       const float* __restrict__ pbb) {
    int blk = blockIdx.x, tid = threadIdx.x;
    if (blk < 512) {
        int i = blk * 256 + tid;              // 131072 float4
        float4 v = last_hh[i];
        v.x = rndtf32(v.x); v.y = rndtf32(v.y); v.z = rndtf32(v.z); v.w = rndtf32(v.w);
        ((float4*)g_h0)[i] = v;
    } else if (blk < 800) {
        int idx = (blk - 512) * 256 + tid;    // 128*576
        int oc = idx / 576, rem = idx - oc * 576;
        int tap = rem >> 6, ic = rem & 63;
        g_w2[idx] = rndtf32(c2_w[oc * 576 + ic * 9 + tap]);
    } else {
        int idx = (blk - 800) * 256 + tid;    // 1024*256
        int b = idx >> 8, o = idx & 255;
        float acc = pbb[o];
        acc = fmaf(pb[b * 3 + 0], pbw[o * 3 + 0], acc);
        acc = fmaf(pb[b * 3 + 1], pbw[o * 3 + 1], acc);
        acc = fmaf(pb[b * 3 + 2], pbw[o * 3 + 2], acc);
        g_x[b * 512 + o] = rndtf32(acc);
    }
}

// ---------------- c1: direct conv -> NHWC (rounded) ----------------
__global__ __launch_bounds__(256) void k_c1(const float* __restrict__ hm,
                                            const float* __restrict__ w,
                                            const float* __restrict__ bias) {
    __shared__ float in_s[2 * 34 * 34];
    __shared__ __align__(16) float w_s[64 * 20];   // stride-20, 16B aligned per oc
    __shared__ float b_s[64];
    int img = blockIdx.x, tid = threadIdx.x;

    for (int i = tid; i < 2 * 34 * 34; i += 256) in_s[i] = 0.f;
    __syncthreads();
    for (int i = tid; i < 2048; i += 256) {
        int ic = i >> 10, p = i & 1023, y = p >> 5, x = p & 31;
        in_s[ic * 1156 + (y + 1) * 34 + (x + 1)] = hm[img * 2048 + i];
    }
    for (int i = tid; i < 1152; i += 256) {
        int oc = i / 18, k = i - oc * 18;
        w_s[oc * 20 + k] = w[i];
    }
    if (tid < 128) {
        int oc = tid >> 1;
        w_s[oc * 20 + 18 + (tid & 1)] = 0.f;
    }
    if (tid < 64) b_s[tid] = bias[tid];
    __syncthreads();

#pragma unroll
    for (int g = 0; g < 4; g++) {
        int p = tid + 256 * g;
        int y = p >> 5, x = p & 31;
        float r[18];
#pragma unroll
        for (int ic = 0; ic < 2; ic++)
#pragma unroll
            for (int kh = 0; kh < 3; kh++)
#pragma unroll
                for (int kw = 0; kw < 3; kw++)
                    r[ic * 9 + kh * 3 + kw] = in_s[ic * 1156 + (y + kh) * 34 + (x + kw)];
        float4 v4[16];
        float* v = (float*)v4;
        for (int oc = 0; oc < 64; oc++) {
            float wr[20];
            const float4* wp = (const float4*)&w_s[oc * 20];
            *(float4*)&wr[0]  = wp[0];
            *(float4*)&wr[4]  = wp[1];
            *(float4*)&wr[8]  = wp[2];
            *(float4*)&wr[12] = wp[3];
            *(float4*)&wr[16] = wp[4];
            float acc = b_s[oc];
#pragma unroll
            for (int k = 0; k < 18; k++) acc = fmaf(r[k], wr[k], acc);
            acc = acc >= 0.f ? acc : LEAK * acc;
            v[oc] = rndtf32(acc);
        }
        float4* dst = (float4*)&g_c1[((long)img * 1024 + p) * 64];
#pragma unroll
        for (int q = 0; q < 16; q++) dst[q] = v4[q];
    }
}

// ---------------- c2: implicit GEMM; A cp.async double-buf, B smem single-buf --
// CTA = (img half: 128 px) x (128 oc). 128 threads, 4 warps, warp 64x64.
__global__ __launch_bounds__(128) void k_c2mma(const float* __restrict__ bias) {
    __shared__ __align__(16) float4 smA[2048];    // 2 x 16KB A buffers
    __shared__ __align__(16) float4 smB[1024];    // 16KB B buffer
    int tid = threadIdx.x, lane = tid & 31, w = tid >> 5;
    int wm = w & 1, wn = w >> 1;
    int img = blockIdx.x >> 1, pxl = (blockIdx.x & 1) * 128;
    int rowL = tid >> 3, c4 = tid & 7;
    uint32_t aBase = smem_u32(smA), bBase = smem_u32(smB);

    float acc[4][8][4] = {};
    float4 rb[8];

    auto cpA = [&](int c, int buf) {
        int t = c >> 1, h = c & 1;
        int ty = t / 3, tx = t - ty * 3;
#pragma unroll
        for (int i = 0; i < 8; i++) {
            int row = rowL + 16 * i;
            int px = pxl + row, oy = px >> 4, ox = px & 15;
            int iy = 2 * oy + ty - 1, ix = 2 * ox + tx - 1;
            int ok = ((unsigned)iy < 32u && (unsigned)ix < 32u) ? 16 : 0;
            const float* src = ok
                ? &g_c1[(((long)img * 32 + iy) * 32 + ix) * 64 + h * 32 + c4 * 4]
                : &g_c1[0];
            uint32_t dst = aBase + buf * 16384 +
                           (uint32_t)(((row << 3) + (c4 ^ (row & 7))) << 4);
            CP_ASYNC16Z(dst, src, ok);
        }
    };
    auto ldgB = [&](int c) {
#pragma unroll
        for (int i = 0; i < 8; i++) {
            int row = rowL + 16 * i;   // oc row
            rb[i] = *(const float4*)&g_w2[row * 576 + c * 32 + c4 * 4];
        }
    };
    auto stsB = [&]() {
#pragma unroll
        for (int i = 0; i < 8; i++) {
            int row = rowL + 16 * i;
            smB[(row << 3) + (c4 ^ (row & 7))] = rb[i];
        }
    };

    ldgB(0);
    cpA(0, 0); CP_COMMIT(); CP_WAIT0();
    stsB();
    __syncthreads();
    for (int s = 0; s < 18; s++) {
        if (s + 1 < 18) { cpA(s + 1, (s + 1) & 1); CP_COMMIT(); ldgB(s + 1); }
        compute_stage(aBase + (s & 1) * 16384, bBase, lane, wm, wn, acc);
        __syncthreads();
        if (s + 1 < 18) { stsB(); CP_WAIT0(); __syncthreads(); }
    }

    int mr = lane >> 2, nc = (lane & 3) * 2;
#pragma unroll
    for (int mt = 0; mt < 4; mt++)
#pragma unroll
        for (int nt = 0; nt < 8; nt++) {
            int m = wm * 64 + mt * 16 + mr;
            int n = wn * 64 + nt * 8 + nc;
#pragma unroll
            for (int q = 0; q < 4; q++) {
                int mm = m + (q >> 1) * 8, oc = n + (q & 1);
                float v = acc[mt][nt][q] + __ldg(&bias[oc]);
                v = v >= 0.f ? v : LEAK * v;
                g_c2[(long)img * 32768 + (long)oc * 256 + (pxl + mm)] = rndtf32(v);
            }
        }
}

// ---------------- generic GEMM: C[M][N] = A[M,K] * B[N,K]^T ----------------
// 128 threads, 4 warps, warp tile 64x64. B is RAW fp32: rounded to tf32 at STS.
__global__ __launch_bounds__(128) void k_gemm_mma(
    const float* __restrict__ A, int lda,
    const float* __restrict__ B, int ldb,
    float* __restrict__ C, int ldc, int S, long cSplit) {
    __shared__ __align__(16) float4 smA[2048];    // 2 x 16KB A buffers
    __shared__ __align__(16) float4 smB[1024];    // 16KB B buffer
    int tid = threadIdx.x, lane = tid & 31, w = tid >> 5;
    int wm = w & 1, wn = w >> 1;
    long m0 = blockIdx.y * 128, n0 = blockIdx.x * 128;
    long kBase = (long)blockIdx.z * S * 32;
    C += (long)blockIdx.z * cSplit;
    const float* Ap = A + m0 * lda + kBase;
    const float* Bp = B + n0 * ldb + kBase;
    int rowL = tid >> 3, c4 = tid & 7;
    uint32_t aBase = smem_u32(smA), bBase = smem_u32(smB);

    float acc[4][8][4] = {};
    float4 rb[8];

    auto cpA = [&](int s, int buf) {
        long k0 = (long)s * 32 + c4 * 4;
#pragma unroll
        for (int i = 0; i < 8; i++) {
            long row = rowL + 16 * i;
            const float* src = Ap + row * lda + k0;
            uint32_t dst = aBase + buf * 16384 +
                           (uint32_t)((((int)row << 3) + (c4 ^ ((int)row & 7))) << 4);
            CP_ASYNC16(dst, src);
        }
    };
    auto ldgB = [&](int s) {
        long k0 = (long)s * 32 + c4 * 4;
#pragma unroll
        for (int i = 0; i < 8; i++) {
            long row = rowL + 16 * i;
            rb[i] = *(const float4*)(Bp + row * ldb + k0);
        }
    };
    auto stsB = [&]() {
#pragma unroll
        for (int i = 0; i < 8; i++) {
            int row = rowL + 16 * i;
            float4 v = rb[i];
            v.x = rndtf32(v.x); v.y = rndtf32(v.y);
            v.z = rndtf32(v.z); v.w = rndtf32(v.w);
            smB[(row << 3) + (c4 ^ (row & 7))] = v;
        }
    };

    ldgB(0);
    cpA(0, 0); CP_COMMIT(); CP_WAIT0();
    stsB();
    __syncthreads();
    for (int s = 0; s < S; s++) {
        if (s + 1 < S) { cpA(s + 1, (s + 1) & 1); CP_COMMIT(); ldgB(s + 1); }
        compute_stage(aBase + (s & 1) * 16384, bBase, lane, wm, wn, acc);
        __syncthreads();
        if (s + 1 < S) { stsB(); CP_WAIT0(); __syncthreads(); }
    }

    int mr = lane >> 2, nc = (lane & 3) * 2;
#pragma unroll
    for (int mt = 0; mt < 4; mt++)
#pragma unroll
        for (int nt = 0; nt < 8; nt++) {
            long m = m0 + wm * 64 + mt * 16 + mr;
            long n = n0 + wn * 64 + nt * 8 + nc;
            *(float2*)&C[m * ldc + n] = make_float2(acc[mt][nt][0], acc[mt][nt][1]);
            *(float2*)&C[(m + 8) * ldc + n] = make_float2(acc[mt][nt][2], acc[mt][nt][3]);
        }
}

// ---------------- c3 split-K reduce + bias + leaky -> x[:, 256:] (rounded) ----
__global__ void k_c3red(const float* __restrict__ bias) {
    int idx = blockIdx.x * 256 + threadIdx.x;   // 1024*256
    int b = idx >> 8, o = idx & 255;
    float s = 0.f;
#pragma unroll
    for (int sp = 0; sp < 16; sp++) s += g_c3p[(long)sp * 262144 + idx];
    s += bias[o];
    s = s >= 0.f ? s : LEAK * s;
    g_x[b * 512 + 256 + o] = rndtf32(s);
}

// ---------------- GRU gates + output ----------------
__global__ void k_gate(const float* __restrict__ h0,
                       const float* __restrict__ bih,
                       const float* __restrict__ bhh,
                       float* __restrict__ out) {
    int idx = blockIdx.x * 256 + threadIdx.x;   // 1024*512
    int b = idx >> 9, j = idx & 511;
    float ir = g_gi[b * 1536 + j]        + bih[j];
    float iz = g_gi[b * 1536 + 512 + j]  + bih[512 + j];
    float in = g_gi[b * 1536 + 1024 + j] + bih[1024 + j];
    float hr = g_gh[b * 1536 + j]        + bhh[j];
    float hz = g_gh[b * 1536 + 512 + j]  + bhh[512 + j];
    float hn = g_gh[b * 1536 + 1024 + j] + bhh[1024 + j];
    float r = 1.f / (1.f + expf(-(ir + hr)));
    float z = 1.f / (1.f + expf(-(iz + hz)));
    float n = tanhf(in + r * hn);
    float h = (1.f - z) * n + z * h0[idx];
    out[idx] = h;
    out[1024 * 512 + idx] = h;
}

// ---------------- launch ----------------
extern "C" void kernel_launch(void* const* d_in, const int* in_sizes, int n_in,
                              void* d_out, int out_size) {
    const float* pre_box   = (const float*)d_in[0];
    const float* heightmap = (const float*)d_in[1];
    const float* last_hh   = (const float*)d_in[2];
    const float* prebox_w  = (const float*)d_in[3];
    const float* prebox_b  = (const float*)d_in[4];
    const float* c1_w      = (const float*)d_in[5];
    const float* c1_b      = (const float*)d_in[6];
    const float* c2_w      = (const float*)d_in[7];
    const float* c2_b      = (const float*)d_in[8];
    const float* c3_w      = (const float*)d_in[9];
    const float* c3_b      = (const float*)d_in[10];
    const float* w_ih      = (const float*)d_in[11];
    const float* w_hh      = (const float*)d_in[12];
    const float* b_ih      = (const float*)d_in[13];
    const float* b_hh      = (const float*)d_in[14];
    float* out = (float*)d_out;

    float *p_c2, *p_c3p, *p_x, *p_gi, *p_gh, *p_h0;
    cudaGetSymbolAddress((void**)&p_c2, g_c2);
    cudaGetSymbolAddress((void**)&p_c3p, g_c3p);
    cudaGetSymbolAddress((void**)&p_x, g_x);
    cudaGetSymbolAddress((void**)&p_gi, g_gi);
    cudaGetSymbolAddress((void**)&p_gh, g_gh);
    cudaGetSymbolAddress((void**)&p_h0, g_h0);

    k_prep<<<1824, 256>>>((const float4*)last_hh, c2_w,
                          pre_box, prebox_w, prebox_b);
    k_c1<<<1024, 256>>>(heightmap, c1_w, c1_b);

    k_c2mma<<<2048, 128>>>(c2_b);

    // c3: M=1024, N=256, K=32768, split-K=16 (S=64 BK32-stages each)
    k_gemm_mma<<<dim3(2, 8, 16), 128>>>(p_c2, 32768, c3_w, 32768,
                                        p_c3p, 256, 64, 262144L);
    k_c3red<<<1024, 256>>>(c3_b);

    // GRU: gi = x*w_ih^T, gh = h0*w_hh^T  (M=1024, N=1536, K=512 -> S=16)
    k_gemm_mma<<<dim3(12, 8, 1), 128>>>(p_x, 512, w_ih, 512, p_gi, 1536, 16, 0);
    k_gemm_mma<<<dim3(12, 8, 1), 128>>>(p_h0, 512, w_hh, 512, p_gh, 1536, 16, 0);

    k_gate<<<2048, 256>>>(last_hh, b_ih, b_hh, out);
}

// round 15
// speedup vs baseline: 1.1395x; 1.0603x over previous
#include <cuda_runtime.h>
#include <cstdint>
#include <math.h>

#define LEAK 0.01f

// Shapes: B=1024, H=512, half=256
// c1: 2->64 3x3 s1 p1 (32x32); c2: 64->128 3x3 s2 p1 (->16x16); c3: 128x16x16->256
// GRU: H=512

// ---------------- static scratch ----------------
__device__ float g_c1 [1024L * 32 * 32 * 64];   // NHWC c1 out (tf32-rounded)
__device__ float g_c2 [1024L * 128 * 256];      // [img][oc][px] (rounded) = c3 A rows
__device__ float g_w2 [128 * 9 * 64];           // c2 weights [oc][tap][ic] (rounded)
__device__ float g_w3 [256L * 32768];           // c3 weights (rounded)
__device__ float g_wih[1536 * 512];             // rounded
__device__ float g_whh[1536 * 512];             // rounded
__device__ float g_h0 [1024 * 512];             // rounded last_hh
__device__ float g_x  [1024 * 512];             // concat(pre_vec, height_vec), rounded
__device__ float g_c3p[16L * 1024 * 256];       // c3 split-K partials [z][b][o]
__device__ float g_gi [1024 * 1536];
__device__ float g_gh [1024 * 1536];

// ---------------- helpers ----------------
__device__ __forceinline__ uint32_t smem_u32(const void* p) {
    uint32_t a;
    asm("{ .reg .u64 t; cvta.to.shared.u64 t, %1; cvt.u32.u64 %0, t; }" : "=r"(a) : "l"(p));
    return a;
}
__device__ __forceinline__ float rndtf32(float f) {
    uint32_t r;
    asm("cvt.rna.tf32.f32 %0, %1;" : "=r"(r) : "f"(f));
    return __uint_as_float(r);
}
__device__ __forceinline__ void mma_tf32(float* c, uint32_t a0, uint32_t a1,
                                         uint32_t a2, uint32_t a3,
                                         uint32_t b0, uint32_t b1) {
    asm volatile(
        "mma.sync.aligned.m16n8k8.row.col.f32.tf32.tf32.f32 "
        "{%0,%1,%2,%3}, {%4,%5,%6,%7}, {%8,%9}, {%0,%1,%2,%3};"
        : "+f"(c[0]), "+f"(c[1]), "+f"(c[2]), "+f"(c[3])
        : "r"(a0), "r"(a1), "r"(a2), "r"(a3), "r"(b0), "r"(b1));
}
#define CP_ASYNC16(dst, src) \
    asm volatile("cp.async.cg.shared.global [%0], [%1], 16;" :: "r"(dst), "l"(src) : "memory")
#define CP_ASYNC16Z(dst, src, sz) \
    asm volatile("cp.async.cg.shared.global [%0], [%1], 16, %2;" :: "r"(dst), "l"(src), "r"(sz) : "memory")
#define CP_COMMIT() asm volatile("cp.async.commit_group;" ::: "memory")
#define CP_WAIT0()  asm volatile("cp.async.wait_group 0;" ::: "memory")

// ---- GEMM core: BM=128 BN=64 BK=32, 2 warps (2M x 1N), warp tile 64x64 ----
// A and B tiles in smem, float4 swizzle: o4 = row*8 + (c4 ^ (row&7))
__device__ __forceinline__ void compute_stage64(uint32_t aS, uint32_t bS, int lane,
                                                int wm, float (&acc)[4][8][4]) {
    int t = lane >> 3, r8 = lane & 7;
    int rowA = wm * 64 + (t & 1) * 8 + r8;
    int thA = t >> 1;
    int rowB = (t >> 1) * 8 + r8;
    int thB = t & 1;
#pragma unroll
    for (int kk = 0; kk < 4; kk++) {
        uint32_t a[4][4];
#pragma unroll
        for (int mt = 0; mt < 4; mt++) {
            uint32_t adr = aS + (uint32_t)(((((rowA + mt * 16) << 3) +
                            ((kk * 2 + thA) ^ r8))) << 4);
            asm volatile("ldmatrix.sync.aligned.m8n8.x4.shared.b16 {%0,%1,%2,%3}, [%4];"
                         : "=r"(a[mt][0]), "=r"(a[mt][1]), "=r"(a[mt][2]), "=r"(a[mt][3])
                         : "r"(adr));
        }
        uint32_t b[8][2];
#pragma unroll
        for (int p = 0; p < 4; p++) {
            uint32_t adr = bS + (uint32_t)(((((rowB + p * 16) << 3) +
                            ((kk * 2 + thB) ^ r8))) << 4);
            uint32_t r0, r1, r2, r3;
            asm volatile("ldmatrix.sync.aligned.m8n8.x4.shared.b16 {%0,%1,%2,%3}, [%4];"
                         : "=r"(r0), "=r"(r1), "=r"(r2), "=r"(r3) : "r"(adr));
            b[p * 2][0] = r0; b[p * 2][1] = r1;
            b[p * 2 + 1][0] = r2; b[p * 2 + 1][1] = r3;
        }
#pragma unroll
        for (int mt = 0; mt < 4; mt++)
#pragma unroll
            for (int nt = 0; nt < 8; nt++)
                mma_tf32(acc[mt][nt], a[mt][0], a[mt][1], a[mt][2], a[mt][3],
                         b[nt][0], b[nt][1]);
    }
}

// Shared pipelined loop for plain GEMM (A and B row-major [rows][K], both pre-rounded)
__device__ __forceinline__ void gemm64_loop(uint32_t aBase, uint32_t bBase,
                                            const float* Ap, long lda,
                                            const float* Bp, long ldb, int S,
                                            int tid, int lane, int wm,
                                            float (&acc)[4][8][4]) {
    int rowL = tid >> 3, c4 = tid & 7;
    auto cpStage = [&](int s, int buf) {
        long k0 = (long)s * 32 + c4 * 4;
        uint32_t aOff = aBase + buf * 16384, bOff = bBase + buf * 8192;
#pragma unroll
        for (int i = 0; i < 16; i++) {
            int row = rowL + 8 * i;
            CP_ASYNC16(aOff + (uint32_t)((((row << 3) + (c4 ^ (row & 7)))) << 4),
                       Ap + (long)row * lda + k0);
        }
#pragma unroll
        for (int i = 0; i < 8; i++) {
            int row = rowL + 8 * i;
            CP_ASYNC16(bOff + (uint32_t)((((row << 3) + (c4 ^ (row & 7)))) << 4),
                       Bp + (long)row * ldb + k0);
        }
    };
    cpStage(0, 0); CP_COMMIT(); CP_WAIT0(); __syncthreads();
    for (int s = 0; s < S; s++) {
        if (s + 1 < S) { cpStage(s + 1, (s + 1) & 1); CP_COMMIT(); }
        compute_stage64(aBase + (s & 1) * 16384, bBase + (s & 1) * 8192,
                        lane, wm, acc);
        if (s + 1 < S) CP_WAIT0();
        __syncthreads();
    }
}

// ---------------- fused prep: rounded copies + repack + prebox ----------------
// blocks: [0,8192) w3 | [8192,8960) wih | [8960,9728) whh | [9728,10240) h0 |
//         [10240,10528) repack | [10528,11552) prebox
__global__ void k_prep(const float4* __restrict__ c3_w,
                       const float4* __restrict__ w_ih,
                       const float4* __restrict__ w_hh,
                       const float4* __restrict__ last_hh,
                       const float* __restrict__ c2_w,
                       const float* __restrict__ pb,
                       const float* __restrict__ pbw,
                       const float* __restrict__ pbb) {
    int blk = blockIdx.x, tid = threadIdx.x;
    if (blk < 9728) {
        const float4* src;
        float4* dst;
        int i;
        if (blk < 8192)      { src = c3_w; dst = (float4*)g_w3;  i = blk * 256 + tid; }
        else if (blk < 8960) { src = w_ih; dst = (float4*)g_wih; i = (blk - 8192) * 256 + tid; }
        else                 { src = w_hh; dst = (float4*)g_whh; i = (blk - 8960) * 256 + tid; }
        float4 v = src[i];
        v.x = rndtf32(v.x); v.y = rndtf32(v.y); v.z = rndtf32(v.z); v.w = rndtf32(v.w);
        dst[i] = v;
    } else if (blk < 10240) {
        int i = (blk - 9728) * 256 + tid;     // 131072 float4
        float4 v = last_hh[i];
        v.x = rndtf32(v.x); v.y = rndtf32(v.y); v.z = rndtf32(v.z); v.w = rndtf32(v.w);
        ((float4*)g_h0)[i] = v;
    } else if (blk < 10528) {
        int idx = (blk - 10240) * 256 + tid;  // 128*576
        int oc = idx / 576, rem = idx - oc * 576;
        int tap = rem >> 6, ic = rem & 63;
        g_w2[idx] = rndtf32(c2_w[oc * 576 + ic * 9 + tap]);
    } else {
        int idx = (blk - 10528) * 256 + tid;  // 1024*256
        int b = idx >> 8, o = idx & 255;
        float acc = pbb[o];
        acc = fmaf(pb[b * 3 + 0], pbw[o * 3 + 0], acc);
        acc = fmaf(pb[b * 3 + 1], pbw[o * 3 + 1], acc);
        acc = fmaf(pb[b * 3 + 2], pbw[o * 3 + 2], acc);
        g_x[b * 512 + o] = rndtf32(acc);
    }
}

// ---------------- c1: direct conv -> NHWC (rounded) ----------------
__global__ __launch_bounds__(256) void k_c1(const float* __restrict__ hm,
                                            const float* __restrict__ w,
                                            const float* __restrict__ bias) {
    __shared__ float in_s[2 * 34 * 34];
    __shared__ __align__(16) float w_s[64 * 20];
    __shared__ float b_s[64];
    int img = blockIdx.x, tid = threadIdx.x;

    for (int i = tid; i < 2 * 34 * 34; i += 256) in_s[i] = 0.f;
    __syncthreads();
    for (int i = tid; i < 2048; i += 256) {
        int ic = i >> 10, p = i & 1023, y = p >> 5, x = p & 31;
        in_s[ic * 1156 + (y + 1) * 34 + (x + 1)] = hm[img * 2048 + i];
    }
    for (int i = tid; i < 1152; i += 256) {
        int oc = i / 18, k = i - oc * 18;
        w_s[oc * 20 + k] = w[i];
    }
    if (tid < 128) {
        int oc = tid >> 1;
        w_s[oc * 20 + 18 + (tid & 1)] = 0.f;
    }
    if (tid < 64) b_s[tid] = bias[tid];
    __syncthreads();

#pragma unroll
    for (int g = 0; g < 4; g++) {
        int p = tid + 256 * g;
        int y = p >> 5, x = p & 31;
        float r[18];
#pragma unroll
        for (int ic = 0; ic < 2; ic++)
#pragma unroll
            for (int kh = 0; kh < 3; kh++)
#pragma unroll
                for (int kw = 0; kw < 3; kw++)
                    r[ic * 9 + kh * 3 + kw] = in_s[ic * 1156 + (y + kh) * 34 + (x + kw)];
        float4 v4[16];
        float* v = (float*)v4;
        for (int oc = 0; oc < 64; oc++) {
            float wr[20];
            const float4* wp = (const float4*)&w_s[oc * 20];
            *(float4*)&wr[0]  = wp[0];
            *(float4*)&wr[4]  = wp[1];
            *(float4*)&wr[8]  = wp[2];
            *(float4*)&wr[12] = wp[3];
            *(float4*)&wr[16] = wp[4];
            float acc = b_s[oc];
#pragma unroll
            for (int k = 0; k < 18; k++) acc = fmaf(r[k], wr[k], acc);
            acc = acc >= 0.f ? acc : LEAK * acc;
            v[oc] = rndtf32(acc);
        }
        float4* dst = (float4*)&g_c1[((long)img * 1024 + p) * 64];
#pragma unroll
        for (int q = 0; q < 16; q++) dst[q] = v4[q];
    }
}

// ---------------- c2: implicit GEMM, 64 threads, dual double-buffer ----------------
// grid (2, 2048): x = oc tile (64), y = img half (128 px). K = 18 stages of 32.
__global__ __launch_bounds__(64) void k_c2mma(const float* __restrict__ bias) {
    __shared__ __align__(16) float4 smA[2048];    // 2 x 16KB
    __shared__ __align__(16) float4 smB[1024];    // 2 x 8KB
    int tid = threadIdx.x, lane = tid & 31, wm = tid >> 5;
    int n0 = blockIdx.x * 64;
    int img = blockIdx.y >> 1, pxl = (blockIdx.y & 1) * 128;
    int rowL = tid >> 3, c4 = tid & 7;
    uint32_t aBase = smem_u32(smA), bBase = smem_u32(smB);

    float acc[4][8][4] = {};

    auto cpStage = [&](int s, int buf) {
        int t = s >> 1, h = s & 1;
        int ty = t / 3, tx = t - ty * 3;
        uint32_t aOff = aBase + buf * 16384, bOff = bBase + buf * 8192;
#pragma unroll
        for (int i = 0; i < 16; i++) {
            int row = rowL + 8 * i;
            int px = pxl + row, oy = px >> 4, ox = px & 15;
            int iy = 2 * oy + ty - 1, ix = 2 * ox + tx - 1;
            int ok = ((unsigned)iy < 32u && (unsigned)ix < 32u) ? 16 : 0;
            const float* src = ok
                ? &g_c1[(((long)img * 32 + iy) * 32 + ix) * 64 + h * 32 + c4 * 4]
                : &g_c1[0];
            CP_ASYNC16Z(aOff + (uint32_t)((((row << 3) + (c4 ^ (row & 7)))) << 4),
                        src, ok);
        }
#pragma unroll
        for (int i = 0; i < 8; i++) {
            int row = rowL + 8 * i;   // oc-local 0..63
            CP_ASYNC16(bOff + (uint32_t)((((row << 3) + (c4 ^ (row & 7)))) << 4),
                       &g_w2[(n0 + row) * 576 + s * 32 + c4 * 4]);
        }
    };

    cpStage(0, 0); CP_COMMIT(); CP_WAIT0(); __syncthreads();
    for (int s = 0; s < 18; s++) {
        if (s + 1 < 18) { cpStage(s + 1, (s + 1) & 1); CP_COMMIT(); }
        compute_stage64(aBase + (s & 1) * 16384, bBase + (s & 1) * 8192,
                        lane, wm, acc);
        if (s + 1 < 18) CP_WAIT0();
        __syncthreads();
    }

    int mr = lane >> 2, nc = (lane & 3) * 2;
#pragma unroll
    for (int mt = 0; mt < 4; mt++)
#pragma unroll
        for (int nt = 0; nt < 8; nt++) {
            int m = wm * 64 + mt * 16 + mr;
            int n = n0 + nt * 8 + nc;
#pragma unroll
            for (int q = 0; q < 4; q++) {
                int mm = m + (q >> 1) * 8, oc = n + (q & 1);
                float v = acc[mt][nt][q] + __ldg(&bias[oc]);
                v = v >= 0.f ? v : LEAK * v;
                g_c2[(long)img * 32768 + (long)oc * 256 + (pxl + mm)] = rndtf32(v);
            }
        }
}

// ---------------- c3 GEMM: grid (4, 8, 16), 64 threads ----------------
__global__ __launch_bounds__(64) void k_gemm64(
    const float* __restrict__ A, int lda,
    const float* __restrict__ B, int ldb,
    float* __restrict__ C, int ldc, int S, long cSplit) {
    __shared__ __align__(16) float4 smA[2048];
    __shared__ __align__(16) float4 smB[1024];
    int tid = threadIdx.x, lane = tid & 31, wm = tid >> 5;
    long m0 = blockIdx.y * 128, n0 = blockIdx.x * 64;
    long kBase = (long)blockIdx.z * S * 32;
    C += (long)blockIdx.z * cSplit;
    const float* Ap = A + m0 * lda + kBase;
    const float* Bp = B + n0 * ldb + kBase;
    uint32_t aBase = smem_u32(smA), bBase = smem_u32(smB);

    float acc[4][8][4] = {};
    gemm64_loop(aBase, bBase, Ap, lda, Bp, ldb, S, tid, lane, wm, acc);

    int mr = lane >> 2, nc = (lane & 3) * 2;
#pragma unroll
    for (int mt = 0; mt < 4; mt++)
#pragma unroll
        for (int nt = 0; nt < 8; nt++) {
            long m = m0 + wm * 64 + mt * 16 + mr;
            long n = n0 + nt * 8 + nc;
            *(float2*)&C[m * ldc + n] = make_float2(acc[mt][nt][0], acc[mt][nt][1]);
            *(float2*)&C[(m + 8) * ldc + n] = make_float2(acc[mt][nt][2], acc[mt][nt][3]);
        }
}

// ---------------- GRU GEMMs fused: grid (24, 8, 2), 64 threads ----------------
// z=0: gi = x * w_ih^T ; z=1: gh = h0 * w_hh^T   (M=1024, N=1536, K=512, S=16)
__global__ __launch_bounds__(64) void k_gru() {
    __shared__ __align__(16) float4 smA[2048];
    __shared__ __align__(16) float4 smB[1024];
    int tid = threadIdx.x, lane = tid & 31, wm = tid >> 5;
    long m0 = blockIdx.y * 128, n0 = blockIdx.x * 64;
    const float* A = blockIdx.z ? g_h0 : g_x;
    const float* B = blockIdx.z ? g_whh : g_wih;
    float* C = blockIdx.z ? g_gh : g_gi;
    const float* Ap = A + m0 * 512;
    const float* Bp = B + n0 * 512;
    uint32_t aBase = smem_u32(smA), bBase = smem_u32(smB);

    float acc[4][8][4] = {};
    gemm64_loop(aBase, bBase, Ap, 512, Bp, 512, 16, tid, lane, wm, acc);

    int mr = lane >> 2, nc = (lane & 3) * 2;
#pragma unroll
    for (int mt = 0; mt < 4; mt++)
#pragma unroll
        for (int nt = 0; nt < 8; nt++) {
            long m = m0 + wm * 64 + mt * 16 + mr;
            long n = n0 + nt * 8 + nc;
            *(float2*)&C[m * 1536 + n] = make_float2(acc[mt][nt][0], acc[mt][nt][1]);
            *(float2*)&C[(m + 8) * 1536 + n] = make_float2(acc[mt][nt][2], acc[mt][nt][3]);
        }
}

// ---------------- c3 split-K reduce + bias + leaky -> x[:, 256:] (rounded) ----
__global__ void k_c3red(const float* __restrict__ bias) {
    int idx = blockIdx.x * 256 + threadIdx.x;   // 1024*256
    int b = idx >> 8, o = idx & 255;
    float s = 0.f;
#pragma unroll
    for (int sp = 0; sp < 16; sp++) s += g_c3p[(long)sp * 262144 + idx];
    s += bias[o];
    s = s >= 0.f ? s : LEAK * s;
    g_x[b * 512 + 256 + o] = rndtf32(s);
}

// ---------------- GRU gates + output ----------------
__global__ void k_gate(const float* __restrict__ h0,
                       const float* __restrict__ bih,
                       const float* __restrict__ bhh,
                       float* __restrict__ out) {
    int idx = blockIdx.x * 256 + threadIdx.x;   // 1024*512
    int b = idx >> 9, j = idx & 511;
    float ir = g_gi[b * 1536 + j]        + bih[j];
    float iz = g_gi[b * 1536 + 512 + j]  + bih[512 + j];
    float in = g_gi[b * 1536 + 1024 + j] + bih[1024 + j];
    float hr = g_gh[b * 1536 + j]        + bhh[j];
    float hz = g_gh[b * 1536 + 512 + j]  + bhh[512 + j];
    float hn = g_gh[b * 1536 + 1024 + j] + bhh[1024 + j];
    float r = 1.f / (1.f + expf(-(ir + hr)));
    float z = 1.f / (1.f + expf(-(iz + hz)));
    float n = tanhf(in + r * hn);
    float h = (1.f - z) * n + z * h0[idx];
    out[idx] = h;
    out[1024 * 512 + idx] = h;
}

// ---------------- launch ----------------
extern "C" void kernel_launch(void* const* d_in, const int* in_sizes, int n_in,
                              void* d_out, int out_size) {
    const float* pre_box   = (const float*)d_in[0];
    const float* heightmap = (const float*)d_in[1];
    const float* last_hh   = (const float*)d_in[2];
    const float* prebox_w  = (const float*)d_in[3];
    const float* prebox_b  = (const float*)d_in[4];
    const float* c1_w      = (const float*)d_in[5];
    const float* c1_b      = (const float*)d_in[6];
    const float* c2_w      = (const float*)d_in[7];
    const float* c2_b      = (const float*)d_in[8];
    const float* c3_w      = (const float*)d_in[9];
    const float* c3_b      = (const float*)d_in[10];
    const float* w_ih      = (const float*)d_in[11];
    const float* w_hh      = (const float*)d_in[12];
    const float* b_ih      = (const float*)d_in[13];
    const float* b_hh      = (const float*)d_in[14];
    float* out = (float*)d_out;

    float *p_c2, *p_c3p, *p_w3;
    cudaGetSymbolAddress((void**)&p_c2, g_c2);
    cudaGetSymbolAddress((void**)&p_c3p, g_c3p);
    cudaGetSymbolAddress((void**)&p_w3, g_w3);

    k_prep<<<11552, 256>>>((const float4*)c3_w, (const float4*)w_ih,
                           (const float4*)w_hh, (const float4*)last_hh,
                           c2_w, pre_box, prebox_w, prebox_b);
    k_c1<<<1024, 256>>>(heightmap, c1_w, c1_b);

    k_c2mma<<<dim3(2, 2048), 64>>>(c2_b);

    // c3: M=1024, N=256, K=32768, split-K=16 (S=64 stages each)
    k_gemm64<<<dim3(4, 8, 16), 64>>>(p_c2, 32768, p_w3, 32768,
                                     p_c3p, 256, 64, 262144L);
    k_c3red<<<1024, 256>>>(c3_b);

    // GRU: both GEMMs in one launch
    k_gru<<<dim3(24, 8, 2), 64>>>();

    k_gate<<<2048, 256>>>(last_hh, b_ih, b_hh, out);
}